// round 8
// baseline (speedup 1.0000x reference)
#include <cuda_runtime.h>
#include <stdint.h>

// Instant-NGP hash-grid interpolation encoding.
// B=262144 points, DIM=3, L=16 levels, T=19 (2^19 tables), F=2 features.
//
// R8: spatial counting-sort preprocessing. Points processed in 15-bit
// spatial-key order (5 bits/dim) so nearby points are adjacent in thread
// order -> low-res levels' corner gathers hit L1 / merge in the miss queue,
// cutting L2 sector traffic (the measured ~61us "base"). Output written at
// original positions (order-independent => deterministic).
// Main kernel = R3 winner (float4 pairing on even g0), reading perm[].

#define NB    262144
#define NL    16
#define TBITS 19
#define TMASK ((1u << TBITS) - 1u)
#define KBITS 5
#define NBINS (1 << (3 * KBITS))   // 32768

__device__ int d_cnt[NBINS];
__device__ int d_off[NBINS];
__device__ int d_perm[NB];

__constant__ float c_res[NL] = {
    16.f, 20.f, 25.f, 32.f, 40.f, 50.f, 64.f, 80.f,
    101.f, 128.f, 161.f, 203.f, 256.f, 322.f, 406.f, 512.f
};

__device__ __forceinline__ int spatial_key(const float* __restrict__ x, int b) {
    const float x0 = __ldg(x + b * 3 + 0);
    const float x1 = __ldg(x + b * 3 + 1);
    const float x2 = __ldg(x + b * 3 + 2);
    int k0 = (int)(x0 * 32.f); k0 = k0 > 31 ? 31 : (k0 < 0 ? 0 : k0);
    int k1 = (int)(x1 * 32.f); k1 = k1 > 31 ? 31 : (k1 < 0 ? 0 : k1);
    int k2 = (int)(x2 * 32.f); k2 = k2 > 31 ? 31 : (k2 < 0 ? 0 : k2);
    return (k0 << (2 * KBITS)) | (k1 << KBITS) | k2;
}

__global__ void zero_kernel() {
    const int i = blockIdx.x * blockDim.x + threadIdx.x;
    if (i < NBINS) d_cnt[i] = 0;
}

__global__ void count_kernel(const float* __restrict__ x) {
    const int b = blockIdx.x * blockDim.x + threadIdx.x;
    if (b < NB) atomicAdd(&d_cnt[spatial_key(x, b)], 1);
}

__global__ void scan_kernel() {   // one block, 1024 threads, 32 bins each
    __shared__ int sh[1024];
    const int t = threadIdx.x;
    const int base = t * 32;
    int s = 0;
#pragma unroll
    for (int i = 0; i < 32; i++) s += d_cnt[base + i];
    sh[t] = s;
    __syncthreads();
    for (int off = 1; off < 1024; off <<= 1) {   // Hillis-Steele inclusive scan
        int v = (t >= off) ? sh[t - off] : 0;
        __syncthreads();
        sh[t] += v;
        __syncthreads();
    }
    int run = (t == 0) ? 0 : sh[t - 1];          // exclusive prefix for chunk
#pragma unroll
    for (int i = 0; i < 32; i++) {
        d_off[base + i] = run;
        run += d_cnt[base + i];
    }
}

__global__ void scatter_kernel(const float* __restrict__ x) {
    const int b = blockIdx.x * blockDim.x + threadIdx.x;
    if (b < NB) {
        const int slot = atomicAdd(&d_off[spatial_key(x, b)], 1);
        d_perm[slot] = b;
    }
}

__global__ void __launch_bounds__(256)
ngp_interp_kernel(const float* __restrict__ x,
                  const float2* __restrict__ tables,
                  float2* __restrict__ out)
{
    const int tid = blockIdx.x * 256 + threadIdx.x;   // tid = bs*16 + l
    const int l = tid & (NL - 1);
    const int bs = tid >> 4;                          // sorted order
    const int b = d_perm[bs];                         // original point id

    const float res = c_res[l];

    const float x0 = __ldg(x + b * 3 + 0);
    const float x1 = __ldg(x + b * 3 + 1);
    const float x2 = __ldg(x + b * 3 + 2);

    const float s0 = x0 * res, s1 = x1 * res, s2 = x2 * res;
    const float g0f = floorf(s0), g1f = floorf(s1), g2f = floorf(s2);
    const float f0 = s0 - g0f, f1 = s1 - g1f, f2 = s2 - g2f;

    const unsigned g0 = (unsigned)g0f;
    const unsigned g1 = (unsigned)g1f;
    const unsigned g2 = (unsigned)g2f;

    const unsigned P1 = 2654435761u, P2 = 805459861u;

    const unsigned h1a = g1 * P1, h1b = (g1 + 1u) * P1;
    const unsigned h2a = g2 * P2, h2b = (g2 + 1u) * P2;

    const float2* __restrict__ tab = tables + ((size_t)l << TBITS);

    const float w0a = 1.f - f0, w0b = f0;
    const float w1a = 1.f - f1, w1b = f1;
    const float w2a = 1.f - f2, w2b = f2;

    unsigned hy[4];
    hy[0] = h1a ^ h2a;  hy[1] = h1b ^ h2a;
    hy[2] = h1a ^ h2b;  hy[3] = h1b ^ h2b;

    float wp[4];
    wp[0] = w1a * w2a;  wp[1] = w1b * w2a;
    wp[2] = w1a * w2b;  wp[3] = w1b * w2b;

    float a0 = 0.f, a1 = 0.f;

    if ((g0 & 1u) == 0u) {
        // g0 even: x-corner pair {idx, idx^1} -> one aligned float4.
        const float4* __restrict__ tab4 = (const float4*)tab;

        unsigned idxA[4];
#pragma unroll
        for (int p = 0; p < 4; p++) idxA[p] = (g0 ^ hy[p]) & TMASK;

        float4 q[4];
#pragma unroll
        for (int p = 0; p < 4; p++) q[p] = __ldg(tab4 + (idxA[p] >> 1));

#pragma unroll
        for (int p = 0; p < 4; p++) {
            const bool hi = (idxA[p] & 1u) != 0u;
            const float vax = hi ? q[p].z : q[p].x;
            const float vay = hi ? q[p].w : q[p].y;
            const float vbx = hi ? q[p].x : q[p].z;
            const float vby = hi ? q[p].y : q[p].w;
            const float wA = w0a * wp[p];
            const float wB = w0b * wp[p];
            a0 += wA * vax + wB * vbx;
            a1 += wA * vay + wB * vby;
        }
    } else {
        // g0 odd: 8 independent float2 gathers.
        const unsigned h0a = g0, h0b = g0 + 1u;

        unsigned idx[8];
#pragma unroll
        for (int p = 0; p < 4; p++) {
            idx[2 * p + 0] = (h0a ^ hy[p]) & TMASK;
            idx[2 * p + 1] = (h0b ^ hy[p]) & TMASK;
        }

        float2 v[8];
#pragma unroll
        for (int i = 0; i < 8; i++) v[i] = __ldg(tab + idx[i]);

#pragma unroll
        for (int p = 0; p < 4; p++) {
            const float wA = w0a * wp[p];
            const float wB = w0b * wp[p];
            a0 += wA * v[2 * p].x + wB * v[2 * p + 1].x;
            a1 += wA * v[2 * p].y + wB * v[2 * p + 1].y;
        }
    }

    // Store at ORIGINAL position: lanes l=0..15 of a point -> 128B line.
    out[b * NL + l] = make_float2(a0, a1);
}

extern "C" void kernel_launch(void* const* d_in, const int* in_sizes, int n_in,
                              void* d_out, int out_size)
{
    const float* x   = (const float*)d_in[0];
    const float* tab = (const float*)d_in[1];
    if (n_in >= 2 && in_sizes[0] > in_sizes[1]) {
        const float* t = x; x = tab; tab = t;
    }

    zero_kernel   <<<NBINS / 256, 256>>>();
    count_kernel  <<<NB / 256, 256>>>(x);
    scan_kernel   <<<1, 1024>>>();
    scatter_kernel<<<NB / 256, 256>>>(x);

    const int total = NB * NL;
    ngp_interp_kernel<<<total / 256, 256>>>(x, (const float2*)tab, (float2*)d_out);
}

// round 10
// speedup vs baseline: 1.0515x; 1.0515x over previous
#include <cuda_runtime.h>
#include <stdint.h>

// Instant-NGP hash-grid interpolation encoding.
// B=262144 points, DIM=3, L=16 levels, T=19 (2^19 tables), F=2 features.
//
// R9: levels 0-7 are served from a densely-indexed, z-pair-duplicated copy
// built per replay by a prep kernel:
//   dense[l][(g0*(R+1)+g1)*R+g2] = float4( tab[h(g0,g1,g2)], tab[h(g0,g1,g2+1)] )
// Hash collisions are irrelevant (value copy). Low levels then need exactly
// 4 aligned float4 loads with spatial locality (L1/L2 line reuse), no hashing.
// Levels 8-15 keep the R3 hash path (float4 pairing on even g0).

#define NB    262144
#define NL    16
#define TBITS 19
#define TMASK ((1u << TBITS) - 1u)
#define NDL   8          // levels 0..7 densified

// Per-level resolutions (floor(16 * (512/16)^(l/15)))
__constant__ float c_res[NL] = {
    16.f, 20.f, 25.f, 32.f, 40.f, 50.f, 64.f, 80.f,
    101.f, 128.f, 161.f, 203.f, 256.f, 322.f, 406.f, 512.f
};

// Dense-level geometry (compile-time).
__constant__ int c_R[NDL]    = { 16, 20, 25, 32, 40, 50, 64, 80 };
// cells per level = (R+1)^2 * R ; offsets are exclusive prefix sums
__constant__ int c_doff[NDL] = { 0, 4624, 13444, 30344, 65192, 132432, 262482, 532882 };
#define DENSE_CELLS 1057762   // total float4 cells (~16.9 MB)

__device__ float4 d_dense[DENSE_CELLS];

// ---------------- prep: build dense tables for levels 0..7 ----------------
__global__ void __launch_bounds__(256)
build_dense_kernel(const float2* __restrict__ tables)
{
    const int i = blockIdx.x * 256 + threadIdx.x;
    if (i >= DENSE_CELLS) return;

    // find level
    int l = NDL - 1;
#pragma unroll
    for (int k = NDL - 1; k > 0; k--)
        if (i < c_doff[k]) l = k - 1;

    const int R   = c_R[l];
    const int rel = i - c_doff[l];

    const int g2 = rel % R;
    const int t  = rel / R;
    const int g1 = t % (R + 1);
    const int g0 = t / (R + 1);

    const unsigned P1 = 2654435761u, P2 = 805459861u;
    const unsigned hxy = (unsigned)g0 ^ ((unsigned)g1 * P1);
    const unsigned ha  = (hxy ^ ((unsigned)g2 * P2)) & TMASK;
    const unsigned hb  = (hxy ^ ((unsigned)(g2 + 1) * P2)) & TMASK;

    const float2* __restrict__ tab = tables + ((size_t)l << TBITS);
    const float2 A = __ldg(tab + ha);
    const float2 B = __ldg(tab + hb);

    d_dense[i] = make_float4(A.x, A.y, B.x, B.y);
}

// ---------------- main ----------------
__global__ void __launch_bounds__(256)
ngp_interp_kernel(const float* __restrict__ x,
                  const float2* __restrict__ tables,
                  float2* __restrict__ out)
{
    const int tid = blockIdx.x * 256 + threadIdx.x;   // tid = b*16 + l
    const int l = tid & (NL - 1);
    const int b = tid >> 4;

    const float res = c_res[l];

    const float x0 = __ldg(x + b * 3 + 0);
    const float x1 = __ldg(x + b * 3 + 1);
    const float x2 = __ldg(x + b * 3 + 2);

    const float s0 = x0 * res, s1 = x1 * res, s2 = x2 * res;
    const float g0f = floorf(s0), g1f = floorf(s1), g2f = floorf(s2);
    const float f0 = s0 - g0f, f1 = s1 - g1f, f2 = s2 - g2f;

    const unsigned g0 = (unsigned)g0f;
    const unsigned g1 = (unsigned)g1f;
    const unsigned g2 = (unsigned)g2f;

    const float w0a = 1.f - f0, w0b = f0;
    const float w1a = 1.f - f1, w1b = f1;
    const float w2a = 1.f - f2;          // z border0 weight; border1 = f2

    float a0, a1;

    if (l < NDL) {
        // ---- dense path: 4 aligned float4 loads, no hashing ----
        const int R = c_R[l];
        const float4* __restrict__ dp = d_dense + c_doff[l];

        const int idx  = ((int)g0 * (R + 1) + (int)g1) * R + (int)g2;
        const int dy   = R;              // g1+1
        const int dx   = (R + 1) * R;    // g0+1

        const float4 q00 = __ldg(dp + idx);
        const float4 q01 = __ldg(dp + idx + dy);
        const float4 q10 = __ldg(dp + idx + dx);
        const float4 q11 = __ldg(dp + idx + dx + dy);

        // z-lerp inside each float4: lo=(z), hi=(z+1)
        const float z00x = w2a * q00.x + f2 * q00.z, z00y = w2a * q00.y + f2 * q00.w;
        const float z01x = w2a * q01.x + f2 * q01.z, z01y = w2a * q01.y + f2 * q01.w;
        const float z10x = w2a * q10.x + f2 * q10.z, z10y = w2a * q10.y + f2 * q10.w;
        const float z11x = w2a * q11.x + f2 * q11.z, z11y = w2a * q11.y + f2 * q11.w;

        a0 = w0a * (w1a * z00x + w1b * z01x) + w0b * (w1a * z10x + w1b * z11x);
        a1 = w0a * (w1a * z00y + w1b * z01y) + w0b * (w1a * z10y + w1b * z11y);
    } else {
        // ---- hash path (R3 winner): float4 pairing on even g0 ----
        const unsigned P1 = 2654435761u, P2 = 805459861u;

        const unsigned h1a = g1 * P1, h1b = (g1 + 1u) * P1;
        const unsigned h2a = g2 * P2, h2b = (g2 + 1u) * P2;

        const float2* __restrict__ tab = tables + ((size_t)l << TBITS);

        unsigned hy[4];
        hy[0] = h1a ^ h2a;  hy[1] = h1b ^ h2a;
        hy[2] = h1a ^ h2b;  hy[3] = h1b ^ h2b;

        const float w2b = f2;
        float wp[4];
        wp[0] = w1a * w2a;  wp[1] = w1b * w2a;
        wp[2] = w1a * w2b;  wp[3] = w1b * w2b;

        a0 = 0.f; a1 = 0.f;

        if ((g0 & 1u) == 0u) {
            const float4* __restrict__ tab4 = (const float4*)tab;

            unsigned idxA[4];
#pragma unroll
            for (int p = 0; p < 4; p++) idxA[p] = (g0 ^ hy[p]) & TMASK;

            float4 q[4];
#pragma unroll
            for (int p = 0; p < 4; p++) q[p] = __ldg(tab4 + (idxA[p] >> 1));

#pragma unroll
            for (int p = 0; p < 4; p++) {
                const bool hi = (idxA[p] & 1u) != 0u;
                const float vax = hi ? q[p].z : q[p].x;
                const float vay = hi ? q[p].w : q[p].y;
                const float vbx = hi ? q[p].x : q[p].z;
                const float vby = hi ? q[p].y : q[p].w;
                const float wA = w0a * wp[p];
                const float wB = w0b * wp[p];
                a0 += wA * vax + wB * vbx;
                a1 += wA * vay + wB * vby;
            }
        } else {
            const unsigned h0a = g0, h0b = g0 + 1u;

            unsigned idx[8];
#pragma unroll
            for (int p = 0; p < 4; p++) {
                idx[2 * p + 0] = (h0a ^ hy[p]) & TMASK;
                idx[2 * p + 1] = (h0b ^ hy[p]) & TMASK;
            }

            float2 v[8];
#pragma unroll
            for (int i = 0; i < 8; i++) v[i] = __ldg(tab + idx[i]);

#pragma unroll
            for (int p = 0; p < 4; p++) {
                const float wA = w0a * wp[p];
                const float wB = w0b * wp[p];
                a0 += wA * v[2 * p].x + wB * v[2 * p + 1].x;
                a1 += wA * v[2 * p].y + wB * v[2 * p + 1].y;
            }
        }
    }

    out[tid] = make_float2(a0, a1);   // out[b,l]: fully coalesced
}

extern "C" void kernel_launch(void* const* d_in, const int* in_sizes, int n_in,
                              void* d_out, int out_size)
{
    const float* x   = (const float*)d_in[0];
    const float* tab = (const float*)d_in[1];
    if (n_in >= 2 && in_sizes[0] > in_sizes[1]) {
        const float* t = x; x = tab; tab = t;
    }

    build_dense_kernel<<<(DENSE_CELLS + 255) / 256, 256>>>((const float2*)tab);

    const int total = NB * NL;
    ngp_interp_kernel<<<total / 256, 256>>>(x, (const float2*)tab, (float2*)d_out);
}

// round 12
// speedup vs baseline: 1.6577x; 1.5765x over previous
#include <cuda_runtime.h>
#include <stdint.h>

// Instant-NGP hash-grid interpolation encoding.
// B=262144 points, DIM=3, L=16 levels, T=19 (2^19 tables), F=2 features.
//
// Structure = R3 winner (78.3us): thread = (point,level); PRIMES[0]==1 so even
// g0 collapses the two x-corners into one aligned float4 load (4 loads), odd
// g0 does 8 float2 gathers. L1tex-wavefront + L2-sector co-bound (validated
// over R2/R4/R5/R6/R8/R9 experiments).
//
// R11 deltas (peripheral only):
//  - cooperative x load: 1 LDG + shuffles instead of 3 broadcast LDGs/thread
//  - __stcs streaming store for out (write-once; don't pollute L2 table lines)

#define NB    262144
#define NL    16
#define TBITS 19
#define TMASK ((1u << TBITS) - 1u)

__constant__ float c_res[NL] = {
    16.f, 20.f, 25.f, 32.f, 40.f, 50.f, 64.f, 80.f,
    101.f, 128.f, 161.f, 203.f, 256.f, 322.f, 406.f, 512.f
};

__global__ void __launch_bounds__(256)
ngp_interp_kernel(const float* __restrict__ x,
                  const float2* __restrict__ tables,
                  float2* __restrict__ out)
{
    const int tid  = blockIdx.x * 256 + threadIdx.x;   // tid = b*16 + l
    const int lane = threadIdx.x & 31;
    const int l = tid & (NL - 1);

    // Warp covers 2 points (16 lanes each). Lanes 0-5 load the 6 floats
    // x[pA*3 .. pA*3+5]; everyone picks their component via shuffle.
    const int pA = (tid & ~31) >> 4;                   // first point of warp
    float xv = 0.f;
    if (lane < 6) xv = __ldg(x + pA * 3 + lane);
    const int cbase = (lane >> 4) * 3;                 // 0 for point A, 3 for B
    const float x0 = __shfl_sync(0xffffffffu, xv, cbase + 0);
    const float x1 = __shfl_sync(0xffffffffu, xv, cbase + 1);
    const float x2 = __shfl_sync(0xffffffffu, xv, cbase + 2);

    const float res = c_res[l];

    const float s0 = x0 * res, s1 = x1 * res, s2 = x2 * res;
    const float g0f = floorf(s0), g1f = floorf(s1), g2f = floorf(s2);
    const float f0 = s0 - g0f, f1 = s1 - g1f, f2 = s2 - g2f;

    const unsigned g0 = (unsigned)g0f;
    const unsigned g1 = (unsigned)g1f;
    const unsigned g2 = (unsigned)g2f;

    const unsigned P1 = 2654435761u, P2 = 805459861u;

    const unsigned h1a = g1 * P1, h1b = (g1 + 1u) * P1;
    const unsigned h2a = g2 * P2, h2b = (g2 + 1u) * P2;

    const float2* __restrict__ tab = tables + ((size_t)l << TBITS);

    const float w0a = 1.f - f0, w0b = f0;
    const float w1a = 1.f - f1, w1b = f1;
    const float w2a = 1.f - f2, w2b = f2;

    unsigned hy[4];
    hy[0] = h1a ^ h2a;  hy[1] = h1b ^ h2a;
    hy[2] = h1a ^ h2b;  hy[3] = h1b ^ h2b;

    float wp[4];
    wp[0] = w1a * w2a;  wp[1] = w1b * w2a;
    wp[2] = w1a * w2b;  wp[3] = w1b * w2b;

    float a0 = 0.f, a1 = 0.f;

    if ((g0 & 1u) == 0u) {
        // g0 even: x-corner pair {idx, idx^1} -> one aligned float4.
        const float4* __restrict__ tab4 = (const float4*)tab;

        unsigned idxA[4];
#pragma unroll
        for (int p = 0; p < 4; p++) idxA[p] = (g0 ^ hy[p]) & TMASK;

        float4 q[4];
#pragma unroll
        for (int p = 0; p < 4; p++) q[p] = __ldg(tab4 + (idxA[p] >> 1));

#pragma unroll
        for (int p = 0; p < 4; p++) {
            const bool hi = (idxA[p] & 1u) != 0u;
            const float vax = hi ? q[p].z : q[p].x;
            const float vay = hi ? q[p].w : q[p].y;
            const float vbx = hi ? q[p].x : q[p].z;
            const float vby = hi ? q[p].y : q[p].w;
            const float wA = w0a * wp[p];
            const float wB = w0b * wp[p];
            a0 += wA * vax + wB * vbx;
            a1 += wA * vay + wB * vby;
        }
    } else {
        // g0 odd: 8 independent float2 gathers.
        const unsigned h0a = g0, h0b = g0 + 1u;

        unsigned idx[8];
#pragma unroll
        for (int p = 0; p < 4; p++) {
            idx[2 * p + 0] = (h0a ^ hy[p]) & TMASK;
            idx[2 * p + 1] = (h0b ^ hy[p]) & TMASK;
        }

        float2 v[8];
#pragma unroll
        for (int i = 0; i < 8; i++) v[i] = __ldg(tab + idx[i]);

#pragma unroll
        for (int p = 0; p < 4; p++) {
            const float wA = w0a * wp[p];
            const float wB = w0b * wp[p];
            a0 += wA * v[2 * p].x + wB * v[2 * p + 1].x;
            a1 += wA * v[2 * p].y + wB * v[2 * p + 1].y;
        }
    }

    // out[b,l] contiguous across the warp; streaming store (write-once data).
    __stcs(out + tid, make_float2(a0, a1));
}

extern "C" void kernel_launch(void* const* d_in, const int* in_sizes, int n_in,
                              void* d_out, int out_size)
{
    const float* x   = (const float*)d_in[0];
    const float* tab = (const float*)d_in[1];
    if (n_in >= 2 && in_sizes[0] > in_sizes[1]) {
        const float* t = x; x = tab; tab = t;
    }

    const int total = NB * NL;
    ngp_interp_kernel<<<total / 256, 256>>>(x, (const float2*)tab, (float2*)d_out);
}

// round 16
// speedup vs baseline: 1.7356x; 1.0470x over previous
#include <cuda_runtime.h>
#include <stdint.h>

// Instant-NGP hash-grid interpolation encoding.
// B=262144 points, DIM=3, L=16 levels, T=19 (2^19-entry tables), F=2 features.
//
// Final kernel (= R3 winner, 78.3us). Thread = (point, level).
// PRIMES[0]==1, so when g0 is even the two x-corners of every (dim1,dim2)
// combo sit at table indices idx and idx^1 -> one aligned float4 load instead
// of two float2 gathers (avg 6 lane-loads/thread vs 8).
//
// Measured floor: L1tex gather wavefronts (~88% of peak) co-bound with L2
// sector traffic (~70%). Verified dead ends: .cg bypass (R4), 256-bit loads
// (R5), predicated unification (R6, reg pressure), spatial sort (R8, cross-SM
// locality is worthless), dense remapped tables (R9, divergence + no lane
// merging), shuffle x-loads / streaming stores (R11, broadcast loads were
// already ~free and shuffles lengthen the critical path).

#define NB   262144
#define NL   16
#define TBITS 19
#define TMASK ((1u << TBITS) - 1u)

__constant__ float c_res[NL] = {
    16.f, 20.f, 25.f, 32.f, 40.f, 50.f, 64.f, 80.f,
    101.f, 128.f, 161.f, 203.f, 256.f, 322.f, 406.f, 512.f
};

__global__ void __launch_bounds__(256)
ngp_interp_kernel(const float* __restrict__ x,
                  const float2* __restrict__ tables,
                  float2* __restrict__ out)
{
    const int tid = blockIdx.x * 256 + threadIdx.x;   // tid = b*16 + l
    const int l = tid & (NL - 1);
    const int b = tid >> 4;

    const float res = c_res[l];

    // 16 lanes share the same point -> broadcast-coalesced, ~free.
    const float x0 = __ldg(x + b * 3 + 0);
    const float x1 = __ldg(x + b * 3 + 1);
    const float x2 = __ldg(x + b * 3 + 2);

    const float s0 = x0 * res, s1 = x1 * res, s2 = x2 * res;
    const float g0f = floorf(s0), g1f = floorf(s1), g2f = floorf(s2);
    const float f0 = s0 - g0f, f1 = s1 - g1f, f2 = s2 - g2f;

    const unsigned g0 = (unsigned)g0f;
    const unsigned g1 = (unsigned)g1f;
    const unsigned g2 = (unsigned)g2f;

    const unsigned P1 = 2654435761u, P2 = 805459861u;

    const unsigned h1a = g1 * P1, h1b = (g1 + 1u) * P1;
    const unsigned h2a = g2 * P2, h2b = (g2 + 1u) * P2;

    const float2* __restrict__ tab = tables + ((size_t)l << TBITS);

    // Weights: border=0 -> (1-f), border=1 -> f.
    const float w0a = 1.f - f0, w0b = f0;
    const float w1a = 1.f - f1, w1b = f1;
    const float w2a = 1.f - f2, w2b = f2;

    // Per-(dim1,dim2) combo: XOR of hash contributions and product weight.
    unsigned hy[4];
    hy[0] = h1a ^ h2a;  hy[1] = h1b ^ h2a;
    hy[2] = h1a ^ h2b;  hy[3] = h1b ^ h2b;

    float wp[4];
    wp[0] = w1a * w2a;  wp[1] = w1b * w2a;
    wp[2] = w1a * w2b;  wp[3] = w1b * w2b;

    float a0 = 0.f, a1 = 0.f;

    if ((g0 & 1u) == 0u) {
        // g0 even: x-corner pair = {idx, idx^1} -> aligned float4.
        const float4* __restrict__ tab4 = (const float4*)tab;

        unsigned idxA[4];
#pragma unroll
        for (int p = 0; p < 4; p++) idxA[p] = (g0 ^ hy[p]) & TMASK;

        float4 q[4];
#pragma unroll
        for (int p = 0; p < 4; p++) q[p] = __ldg(tab4 + (idxA[p] >> 1));

#pragma unroll
        for (int p = 0; p < 4; p++) {
            const bool hi = (idxA[p] & 1u) != 0u;
            // corner A = border0 (weight w0a) lives at idxA; B at idxA^1.
            const float vax = hi ? q[p].z : q[p].x;
            const float vay = hi ? q[p].w : q[p].y;
            const float vbx = hi ? q[p].x : q[p].z;
            const float vby = hi ? q[p].y : q[p].w;
            const float wA = w0a * wp[p];
            const float wB = w0b * wp[p];
            a0 += wA * vax + wB * vbx;
            a1 += wA * vay + wB * vby;
        }
    } else {
        // g0 odd: corners not adjacent -> 8 independent float2 gathers.
        const unsigned h0a = g0, h0b = g0 + 1u;

        unsigned idx[8];
#pragma unroll
        for (int p = 0; p < 4; p++) {
            idx[2 * p + 0] = (h0a ^ hy[p]) & TMASK;
            idx[2 * p + 1] = (h0b ^ hy[p]) & TMASK;
        }

        float2 v[8];
#pragma unroll
        for (int i = 0; i < 8; i++) v[i] = __ldg(tab + idx[i]);

#pragma unroll
        for (int p = 0; p < 4; p++) {
            const float wA = w0a * wp[p];
            const float wB = w0b * wp[p];
            a0 += wA * v[2 * p].x + wB * v[2 * p + 1].x;
            a1 += wA * v[2 * p].y + wB * v[2 * p + 1].y;
        }
    }

    out[tid] = make_float2(a0, a1);   // out[b,l]: fully coalesced
}

extern "C" void kernel_launch(void* const* d_in, const int* in_sizes, int n_in,
                              void* d_out, int out_size)
{
    // Robust input-order detection: x has 262144*3 = 786432 elements,
    // tables has 16*2^19*2 = 16777216 elements.
    const float* x   = (const float*)d_in[0];
    const float* tab = (const float*)d_in[1];
    if (n_in >= 2 && in_sizes[0] > in_sizes[1]) {
        const float* t = x; x = tab; tab = t;
    }

    const int total = NB * NL;
    ngp_interp_kernel<<<total / 256, 256>>>(x, (const float2*)tab, (float2*)d_out);
}